// round 4
// baseline (speedup 1.0000x reference)
#include <cuda_runtime.h>
#include <stdint.h>

// ---------------------------------------------------------------------------
// PGExplainer forward: masked_adj = adj * 0.5*(mask + mask^T)
//   mask[c,r] = sum of concrete-sample values over edges (c,r)
//   adj[c,r]  = edge multiplicity
// Identity: out[c,r] = sum_{edges e at (c,r)} 0.5*(mask[c,r]+mask[r,c])
// ---------------------------------------------------------------------------

#define N_NODES 10000
#define N_EDGES 640000
#define D_EMB   128
#define HID     64

#define OUT_ELEMS ((size_t)N_NODES * N_NODES)   // 1e8 floats = 400 MB

// Scratch (device globals, zero-initialized at load; g_mask is restored to
// zero at touched positions at the end of every kernel_launch call).
__device__ float g_A[N_NODES * HID];
__device__ float g_B[N_NODES * HID];
__device__ float g_noise[N_EDGES];
__device__ int2  g_ci[N_EDGES];        // decoded (col,row), clamped valid
__device__ int   g_is64;               // 1 if edge_index buffer is int64
__device__ float g_mask[OUT_ELEMS];    // 400 MB

// ---------------------------------------------------------------------------
// K_detect: decide whether the edge_index buffer is int64 or int32.
// int64 node ids < 2^32 => all odd 32-bit words are zero.
// ---------------------------------------------------------------------------
__global__ void k_detect(const uint32_t* __restrict__ ew) {
    __shared__ int any_nonzero;
    if (threadIdx.x == 0) any_nonzero = 0;
    __syncthreads();
    for (int i = threadIdx.x; i < 4096; i += blockDim.x) {
        if (ew[2 * i + 1] != 0u) any_nonzero = 1;
    }
    __syncthreads();
    if (threadIdx.x == 0) g_is64 = any_nonzero ? 0 : 1;
}

// ---------------------------------------------------------------------------
// K_decode: expand edge_index (either width) into clamped int2 pairs.
// ---------------------------------------------------------------------------
__global__ void k_decode(const void* __restrict__ ei_raw) {
    int e = blockIdx.x * blockDim.x + threadIdx.x;
    if (e >= N_EDGES) return;
    int c, r;
    if (g_is64) {
        const long long* p = (const long long*)ei_raw;
        c = (int)p[e];
        r = (int)p[N_EDGES + e];
    } else {
        const int* p = (const int*)ei_raw;
        c = p[e];
        r = p[N_EDGES + e];
    }
    c = min(max(c, 0), N_NODES - 1);
    r = min(max(r, 0), N_NODES - 1);
    g_ci[e] = make_int2(c, r);
}

// ---------------------------------------------------------------------------
// K_zero: graph-capturable zeroing of d_out.
// ---------------------------------------------------------------------------
__global__ void k_zero(float4* __restrict__ out, size_t n4) {
    size_t i = (size_t)blockIdx.x * blockDim.x + threadIdx.x;
    if (i < n4) out[i] = make_float4(0.f, 0.f, 0.f, 0.f);
}

// ---------------------------------------------------------------------------
// threefry2x32 core (JAX rotation/key schedule), key = (0, 42)
// ---------------------------------------------------------------------------
__device__ __forceinline__ uint32_t rotl32(uint32_t x, int d) {
    return (x << d) | (x >> (32 - d));
}

__device__ __forceinline__ void threefry2x32(uint32_t k0, uint32_t k1,
                                             uint32_t x0, uint32_t x1,
                                             uint32_t& o0, uint32_t& o1) {
    uint32_t ks0 = k0, ks1 = k1, ks2 = k0 ^ k1 ^ 0x1BD11BDAu;
#define TF_R4(a, b, c, d)                            \
    x0 += x1; x1 = rotl32(x1, a); x1 ^= x0;          \
    x0 += x1; x1 = rotl32(x1, b); x1 ^= x0;          \
    x0 += x1; x1 = rotl32(x1, c); x1 ^= x0;          \
    x0 += x1; x1 = rotl32(x1, d); x1 ^= x0;
    x0 += ks0; x1 += ks1;
    TF_R4(13, 15, 26, 6);  x0 += ks1; x1 += ks2 + 1u;
    TF_R4(17, 29, 16, 24); x0 += ks2; x1 += ks0 + 2u;
    TF_R4(13, 15, 26, 6);  x0 += ks0; x1 += ks1 + 3u;
    TF_R4(17, 29, 16, 24); x0 += ks1; x1 += ks2 + 4u;
    TF_R4(13, 15, 26, 6);  x0 += ks2; x1 += ks0 + 5u;
#undef TF_R4
    o0 = x0; o1 = x1;
}

__device__ __forceinline__ float noise_from_bits(uint32_t bits) {
    // JAX uniform: bitcast(bits>>9 | 0x3f800000) - 1  in [0,1)
    float u = __uint_as_float((bits >> 9) | 0x3f800000u) - 1.0f;
    return logf(u) - log1pf(-u);   // u==0 -> -inf -> sigmoid -> 0 (matches ref)
}

// ---------------------------------------------------------------------------
// K_noise: PARTITIONABLE threefry stream (modern JAX default).
// counts = 64-bit iota -> (hi, lo) = (0, e); bits = out0 ^ out1 (32-bit path).
// ---------------------------------------------------------------------------
__global__ void k_noise() {
    int e = blockIdx.x * blockDim.x + threadIdx.x;
    if (e >= N_EDGES) return;
    uint32_t o0, o1;
    threefry2x32(0u, 42u, 0u, (uint32_t)e, o0, o1);
    g_noise[e] = noise_from_bits(o0 ^ o1);
}

// ---------------------------------------------------------------------------
// K_pre: A[n] = embed[n] @ W1[0:128], B[n] = embed[n] @ W1[128:256]
// ---------------------------------------------------------------------------
__global__ void k_pre(const float* __restrict__ embed, const float* __restrict__ W1) {
    __shared__ float es[4 * D_EMB];
    int h   = threadIdx.x & 63;
    int sub = threadIdx.x >> 6;
    for (int n0 = blockIdx.x * 4; n0 < N_NODES; n0 += gridDim.x * 4) {
        __syncthreads();
        int base = n0 * D_EMB;
        es[threadIdx.x]       = embed[base + threadIdx.x];
        es[threadIdx.x + 256] = embed[base + threadIdx.x + 256];
        __syncthreads();
        int n = n0 + sub;
        if (n < N_NODES) {
            float a = 0.f, b = 0.f;
            #pragma unroll 8
            for (int d = 0; d < D_EMB; d++) {
                float e = es[sub * D_EMB + d];
                a = fmaf(e, __ldg(&W1[d * HID + h]), a);
                b = fmaf(e, __ldg(&W1[(d + D_EMB) * HID + h]), b);
            }
            g_A[n * HID + h] = a;
            g_B[n * HID + h] = b;
        }
    }
}

// ---------------------------------------------------------------------------
// K_edge: warp per edge. h = relu(A[col]+B[row]+b1); la = h.W2 + b2;
// v = sigmoid(noise + la); atomicAdd into g_mask[col, row].
// ---------------------------------------------------------------------------
__global__ void k_edge(const float* __restrict__ b1,
                       const float* __restrict__ W2,
                       const float* __restrict__ b2) {
    int gw   = (blockIdx.x * blockDim.x + threadIdx.x) >> 5;
    int lane = threadIdx.x & 31;
    if (gw >= N_EDGES) return;
    int2 cr = g_ci[gw];
    int c = cr.x, r = cr.y;

    float a0 = g_A[c * HID + lane]      + g_B[r * HID + lane]      + __ldg(&b1[lane]);
    float a1 = g_A[c * HID + 32 + lane] + g_B[r * HID + 32 + lane] + __ldg(&b1[32 + lane]);
    float la = fmaxf(a0, 0.f) * __ldg(&W2[lane]) + fmaxf(a1, 0.f) * __ldg(&W2[32 + lane]);
    #pragma unroll
    for (int o = 16; o; o >>= 1) la += __shfl_xor_sync(0xffffffffu, la, o);

    if (lane == 0) {
        float x = g_noise[gw] + la + __ldg(&b2[0]);
        float v = 1.0f / (1.0f + expf(-x));   // sigmoid; -inf -> 0 exactly
        atomicAdd(&g_mask[(size_t)c * N_NODES + r], v);
    }
}

// ---------------------------------------------------------------------------
// K_sym: per edge, out[c,r] += 0.5*(mask[c,r] + mask[r,c]).
// Summed over duplicate edges this equals adj * sym_mask (reference).
// ---------------------------------------------------------------------------
__global__ void k_sym(float* __restrict__ out) {
    int e = blockIdx.x * blockDim.x + threadIdx.x;
    if (e >= N_EDGES) return;
    int2 cr = g_ci[e];
    float m = g_mask[(size_t)cr.x * N_NODES + cr.y] +
              g_mask[(size_t)cr.y * N_NODES + cr.x];
    atomicAdd(&out[(size_t)cr.x * N_NODES + cr.y], 0.5f * m);
}

// ---------------------------------------------------------------------------
// K_clear: restore g_mask to zero at every touched position so the next
// graph replay starts from a clean scratch.
// ---------------------------------------------------------------------------
__global__ void k_clear() {
    int e = blockIdx.x * blockDim.x + threadIdx.x;
    if (e >= N_EDGES) return;
    int2 cr = g_ci[e];
    g_mask[(size_t)cr.x * N_NODES + cr.y] = 0.0f;
}

// ---------------------------------------------------------------------------
extern "C" void kernel_launch(void* const* d_in, const int* in_sizes, int n_in,
                              void* d_out, int out_size) {
    const float* embed = (const float*)d_in[0];
    const void*  ei    = d_in[1];
    const float* W1    = (const float*)d_in[2];
    const float* b1    = (const float*)d_in[3];
    const float* W2    = (const float*)d_in[4];
    const float* b2    = (const float*)d_in[5];
    float*       out   = (float*)d_out;

    // 0. sniff edge_index dtype, decode + clamp into int2 pairs
    k_detect<<<1, 256>>>((const uint32_t*)ei);
    k_decode<<<(N_EDGES + 255) / 256, 256>>>(ei);

    // 1. zero the dense output (dominant cost: 400 MB)
    {
        size_t n4 = OUT_ELEMS / 4;
        int blocks = (int)((n4 + 255) / 256);
        k_zero<<<blocks, 256>>>((float4*)out, n4);
    }

    // 2. per-node halves of the first GEMM
    k_pre<<<512, 256>>>(embed, W1);

    // 3. JAX-exact logistic noise per edge (partitionable threefry stream)
    k_noise<<<(N_EDGES + 255) / 256, 256>>>();

    // 4. per-edge logit + concrete sample -> scatter into mask scratch
    {
        long long threads = (long long)N_EDGES * 32;
        int blocks = (int)((threads + 255) / 256);
        k_edge<<<blocks, 256>>>(b1, W2, b2);
    }

    // 5. symmetrize + multiplicity, accumulate into output
    k_sym<<<(N_EDGES + 255) / 256, 256>>>(out);

    // 6. restore scratch to all-zero for the next replay
    k_clear<<<(N_EDGES + 255) / 256, 256>>>();
}

// round 5
// speedup vs baseline: 1.0301x; 1.0301x over previous
#include <cuda_runtime.h>
#include <stdint.h>

// ---------------------------------------------------------------------------
// PGExplainer forward: masked_adj = adj * 0.5*(mask + mask^T)
// Identity: out[c,r] = sum_{edges e at (c,r)} 0.5*(mask[c,r]+mask[r,c])
// ---------------------------------------------------------------------------

#define N_NODES 10000
#define N_EDGES 640000
#define D_EMB   128
#define HID     64

#define OUT_ELEMS ((size_t)N_NODES * N_NODES)   // 1e8 floats = 400 MB
#define OUT_F4    (OUT_ELEMS / 4)               // 25,000,000 float4

#define EDGE_BLOCKS (N_EDGES / 8)               // 80,000 blocks, 8 edges each
#define ZPB 313                                 // float4 zero-slab per block (80000*313 >= 25M)

// Scratch (device globals, zero-initialized at load; g_mask is restored to
// zero at touched positions at the end of every kernel_launch call).
__device__ float g_A[N_NODES * HID];
__device__ float g_B[N_NODES * HID];
__device__ float g_noise[N_EDGES];
__device__ int2  g_ci[N_EDGES];        // decoded (col,row), clamped valid
__device__ int   g_is64;               // 1 if edge_index buffer is int64
__device__ float g_mask[OUT_ELEMS];    // 400 MB

// ---------------------------------------------------------------------------
// threefry2x32 core (JAX rotation/key schedule), key = (0, 42)
// ---------------------------------------------------------------------------
__device__ __forceinline__ uint32_t rotl32(uint32_t x, int d) {
    return (x << d) | (x >> (32 - d));
}

__device__ __forceinline__ void threefry2x32(uint32_t k0, uint32_t k1,
                                             uint32_t x0, uint32_t x1,
                                             uint32_t& o0, uint32_t& o1) {
    uint32_t ks0 = k0, ks1 = k1, ks2 = k0 ^ k1 ^ 0x1BD11BDAu;
#define TF_R4(a, b, c, d)                            \
    x0 += x1; x1 = rotl32(x1, a); x1 ^= x0;          \
    x0 += x1; x1 = rotl32(x1, b); x1 ^= x0;          \
    x0 += x1; x1 = rotl32(x1, c); x1 ^= x0;          \
    x0 += x1; x1 = rotl32(x1, d); x1 ^= x0;
    x0 += ks0; x1 += ks1;
    TF_R4(13, 15, 26, 6);  x0 += ks1; x1 += ks2 + 1u;
    TF_R4(17, 29, 16, 24); x0 += ks2; x1 += ks0 + 2u;
    TF_R4(13, 15, 26, 6);  x0 += ks0; x1 += ks1 + 3u;
    TF_R4(17, 29, 16, 24); x0 += ks1; x1 += ks2 + 4u;
    TF_R4(13, 15, 26, 6);  x0 += ks2; x1 += ks0 + 5u;
#undef TF_R4
    o0 = x0; o1 = x1;
}

__device__ __forceinline__ float noise_from_bits(uint32_t bits) {
    // JAX uniform: bitcast(bits>>9 | 0x3f800000) - 1  in [0,1)
    float u = __uint_as_float((bits >> 9) | 0x3f800000u) - 1.0f;
    return logf(u) - log1pf(-u);   // u==0 -> -inf -> sigmoid -> 0 (matches ref)
}

// ---------------------------------------------------------------------------
// K_detect: decide whether the edge_index buffer is int64 or int32.
// int64 node ids < 2^32 => all odd 32-bit words are zero.
// ---------------------------------------------------------------------------
__global__ void k_detect(const uint32_t* __restrict__ ew) {
    __shared__ int any_nonzero;
    if (threadIdx.x == 0) any_nonzero = 0;
    __syncthreads();
    for (int i = threadIdx.x; i < 4096; i += blockDim.x) {
        if (ew[2 * i + 1] != 0u) any_nonzero = 1;
    }
    __syncthreads();
    if (threadIdx.x == 0) g_is64 = any_nonzero ? 0 : 1;
}

// ---------------------------------------------------------------------------
// K_decode_noise: decode+clamp edge indices AND generate the partitionable
// threefry noise stream (bits = o0 ^ o1, counter (0, e)) in one pass.
// ---------------------------------------------------------------------------
__global__ void k_decode_noise(const void* __restrict__ ei_raw) {
    int e = blockIdx.x * blockDim.x + threadIdx.x;
    if (e >= N_EDGES) return;
    int c, r;
    if (g_is64) {
        const long long* p = (const long long*)ei_raw;
        c = (int)p[e];
        r = (int)p[N_EDGES + e];
    } else {
        const int* p = (const int*)ei_raw;
        c = p[e];
        r = p[N_EDGES + e];
    }
    c = min(max(c, 0), N_NODES - 1);
    r = min(max(r, 0), N_NODES - 1);
    g_ci[e] = make_int2(c, r);

    uint32_t o0, o1;
    threefry2x32(0u, 42u, 0u, (uint32_t)e, o0, o1);
    g_noise[e] = noise_from_bits(o0 ^ o1);
}

// ---------------------------------------------------------------------------
// K_pre: A[n] = embed[n] @ W1[0:128], B[n] = embed[n] @ W1[128:256]
// 625 blocks x 256 threads; block = 16 nodes x 16 h-quads (float4 outputs).
// W1 (64 KB) stays L1-resident; embed tile staged in smem.
// ---------------------------------------------------------------------------
__global__ void __launch_bounds__(256) k_pre(const float* __restrict__ embed,
                                             const float* __restrict__ W1) {
    __shared__ float es[16 * D_EMB];                  // 8 KB
    int hq  = threadIdx.x & 15;                       // h-quad: h = hq*4
    int sub = threadIdx.x >> 4;                       // node slot 0..15
    int n0  = blockIdx.x * 16;

    // stage 16 embedding rows (2048 floats = 512 float4)
    const float4* emb4 = (const float4*)(embed + (size_t)n0 * D_EMB);
    float4* es4 = (float4*)es;
    es4[threadIdx.x]       = emb4[threadIdx.x];
    es4[threadIdx.x + 256] = emb4[threadIdx.x + 256];
    __syncthreads();

    const float4* W14 = (const float4*)W1;            // [256][16] float4
    float4 a = make_float4(0.f, 0.f, 0.f, 0.f);
    float4 b = make_float4(0.f, 0.f, 0.f, 0.f);
    const float* er = es + sub * D_EMB;
    #pragma unroll 4
    for (int d = 0; d < D_EMB; d++) {
        float  e  = er[d];
        float4 wa = __ldg(&W14[d * 16 + hq]);
        float4 wb = __ldg(&W14[(d + D_EMB) * 16 + hq]);
        a.x = fmaf(e, wa.x, a.x); a.y = fmaf(e, wa.y, a.y);
        a.z = fmaf(e, wa.z, a.z); a.w = fmaf(e, wa.w, a.w);
        b.x = fmaf(e, wb.x, b.x); b.y = fmaf(e, wb.y, b.y);
        b.z = fmaf(e, wb.z, b.z); b.w = fmaf(e, wb.w, b.w);
    }
    int n = n0 + sub;
    ((float4*)g_A)[n * 16 + hq] = a;
    ((float4*)g_B)[n * 16 + hq] = b;
}

// ---------------------------------------------------------------------------
// K_fused: (a) zero a slab of d_out (replaces the serial 400 MB memset),
//          (b) warp-per-edge MLP + concrete sample + scatter into g_mask.
// The zero stores are fire-and-forget DRAM writes that overlap the
// L2-load/atomic-bound edge work inside the same kernel.
// ---------------------------------------------------------------------------
__global__ void __launch_bounds__(256) k_fused(const float* __restrict__ b1,
                                               const float* __restrict__ W2,
                                               const float* __restrict__ b2,
                                               float4* __restrict__ out) {
    // ---- zero slab ----
    size_t zbase = (size_t)blockIdx.x * ZPB;
    const float4 z4 = make_float4(0.f, 0.f, 0.f, 0.f);
    #pragma unroll
    for (int i = 0; i < 2; i++) {
        size_t idx = zbase + threadIdx.x + i * 256;
        if (threadIdx.x + i * 256 < ZPB && idx < OUT_F4) out[idx] = z4;
    }

    // ---- edge work: 8 edges per block, warp per edge ----
    int gw   = blockIdx.x * 8 + (threadIdx.x >> 5);
    int lane = threadIdx.x & 31;
    if (gw >= N_EDGES) return;
    int2 cr = g_ci[gw];
    int c = cr.x, r = cr.y;

    float a0 = g_A[c * HID + lane]      + g_B[r * HID + lane]      + __ldg(&b1[lane]);
    float a1 = g_A[c * HID + 32 + lane] + g_B[r * HID + 32 + lane] + __ldg(&b1[32 + lane]);
    float la = fmaxf(a0, 0.f) * __ldg(&W2[lane]) + fmaxf(a1, 0.f) * __ldg(&W2[32 + lane]);
    #pragma unroll
    for (int o = 16; o; o >>= 1) la += __shfl_xor_sync(0xffffffffu, la, o);

    if (lane == 0) {
        float x = g_noise[gw] + la + __ldg(&b2[0]);
        float v = 1.0f / (1.0f + expf(-x));   // sigmoid; -inf -> 0 exactly
        atomicAdd(&g_mask[(size_t)c * N_NODES + r], v);
    }
}

// ---------------------------------------------------------------------------
// K_sym: per edge, out[c,r] += 0.5*(mask[c,r] + mask[r,c]).
// Summed over duplicate edges this equals adj * sym_mask (reference).
// ---------------------------------------------------------------------------
__global__ void k_sym(float* __restrict__ out) {
    int e = blockIdx.x * blockDim.x + threadIdx.x;
    if (e >= N_EDGES) return;
    int2 cr = g_ci[e];
    float m = g_mask[(size_t)cr.x * N_NODES + cr.y] +
              g_mask[(size_t)cr.y * N_NODES + cr.x];
    atomicAdd(&out[(size_t)cr.x * N_NODES + cr.y], 0.5f * m);
}

// ---------------------------------------------------------------------------
// K_clear: restore g_mask to zero at every touched position so the next
// graph replay starts from a clean scratch.
// ---------------------------------------------------------------------------
__global__ void k_clear() {
    int e = blockIdx.x * blockDim.x + threadIdx.x;
    if (e >= N_EDGES) return;
    int2 cr = g_ci[e];
    g_mask[(size_t)cr.x * N_NODES + cr.y] = 0.0f;
}

// ---------------------------------------------------------------------------
extern "C" void kernel_launch(void* const* d_in, const int* in_sizes, int n_in,
                              void* d_out, int out_size) {
    const float* embed = (const float*)d_in[0];
    const void*  ei    = d_in[1];
    const float* W1    = (const float*)d_in[2];
    const float* b1    = (const float*)d_in[3];
    const float* W2    = (const float*)d_in[4];
    const float* b2    = (const float*)d_in[5];
    float*       out   = (float*)d_out;

    // 0. sniff edge_index dtype; decode + clamp + threefry noise in one pass
    k_detect<<<1, 256>>>((const uint32_t*)ei);
    k_decode_noise<<<(N_EDGES + 255) / 256, 256>>>(ei);

    // 1. per-node halves of the first GEMM (high-occupancy float4 version)
    k_pre<<<N_NODES / 16, 256>>>(embed, W1);

    // 2. fused: zero d_out (400 MB) + per-edge MLP/sample/scatter
    k_fused<<<EDGE_BLOCKS, 256>>>(b1, W2, b2, (float4*)out);

    // 3. symmetrize + multiplicity, accumulate into output
    k_sym<<<(N_EDGES + 255) / 256, 256>>>(out);

    // 4. restore scratch to all-zero for the next replay
    k_clear<<<(N_EDGES + 255) / 256, 256>>>();
}

// round 6
// speedup vs baseline: 1.1818x; 1.1473x over previous
#include <cuda_runtime.h>
#include <stdint.h>

// ---------------------------------------------------------------------------
// PGExplainer forward: masked_adj = adj * 0.5*(mask + mask^T)
// out[c,r] = cnt(c,r) * 0.5 * (S(c,r) + S(r,c)),  S = sum of sampled values
// Implementation: hash table keyed by cell id (c*N+r) holding (S, cnt);
// final write is an idempotent plain store (duplicates store the same value).
// ---------------------------------------------------------------------------

#define N_NODES 10000
#define N_EDGES 640000
#define D_EMB   128
#define HID     64

#define OUT_ELEMS ((size_t)N_NODES * N_NODES)   // 1e8 floats = 400 MB
#define OUT_F4    (OUT_ELEMS / 4)               // 25,000,000 float4

#define EPB          32                          // edges per block (8 warps x 4)
#define FUSED_BLOCKS (N_EDGES / EPB)             // 20,000
#define ZPB4         1250                        // float4 zero-slab per block (exact: 20000*1250 = 25M)

#define HCAP  (1 << 21)                          // hash capacity (2M slots, load 0.3)
#define HMASK (HCAP - 1)

// Scratch (device globals, zero-initialized at load; hash table is cleared
// at the start of every kernel_launch call).
__device__ float g_A[N_NODES * HID];
__device__ float g_B[N_NODES * HID];
__device__ float g_noise[N_EDGES];
__device__ int2  g_ci[N_EDGES];        // decoded (col,row), clamped valid
__device__ int   g_slot[N_EDGES];      // hash slot of edge's own cell
__device__ int   g_is64;               // 1 if edge_index buffer is int64
__device__ int   g_keys[HCAP];         // -1 = empty
__device__ float g_sums[HCAP];
__device__ int   g_cnts[HCAP];

__device__ __forceinline__ uint32_t cell_hash(int key) {
    return ((uint32_t)key * 0x9E3779B1u) >> (32 - 21);   // top 21 bits
}

// ---------------------------------------------------------------------------
// threefry2x32 core (JAX rotation/key schedule), key = (0, 42)
// ---------------------------------------------------------------------------
__device__ __forceinline__ uint32_t rotl32(uint32_t x, int d) {
    return (x << d) | (x >> (32 - d));
}

__device__ __forceinline__ void threefry2x32(uint32_t k0, uint32_t k1,
                                             uint32_t x0, uint32_t x1,
                                             uint32_t& o0, uint32_t& o1) {
    uint32_t ks0 = k0, ks1 = k1, ks2 = k0 ^ k1 ^ 0x1BD11BDAu;
#define TF_R4(a, b, c, d)                            \
    x0 += x1; x1 = rotl32(x1, a); x1 ^= x0;          \
    x0 += x1; x1 = rotl32(x1, b); x1 ^= x0;          \
    x0 += x1; x1 = rotl32(x1, c); x1 ^= x0;          \
    x0 += x1; x1 = rotl32(x1, d); x1 ^= x0;
    x0 += ks0; x1 += ks1;
    TF_R4(13, 15, 26, 6);  x0 += ks1; x1 += ks2 + 1u;
    TF_R4(17, 29, 16, 24); x0 += ks2; x1 += ks0 + 2u;
    TF_R4(13, 15, 26, 6);  x0 += ks0; x1 += ks1 + 3u;
    TF_R4(17, 29, 16, 24); x0 += ks1; x1 += ks2 + 4u;
    TF_R4(13, 15, 26, 6);  x0 += ks2; x1 += ks0 + 5u;
#undef TF_R4
    o0 = x0; o1 = x1;
}

__device__ __forceinline__ float noise_from_bits(uint32_t bits) {
    float u = __uint_as_float((bits >> 9) | 0x3f800000u) - 1.0f;   // [0,1)
    return logf(u) - log1pf(-u);   // u==0 -> -inf -> sigmoid -> 0 (matches ref)
}

// ---------------------------------------------------------------------------
// K_detect: int64 vs int32 edge_index (int64 ids < 2^32 => odd words all 0).
// ---------------------------------------------------------------------------
__global__ void k_detect(const uint32_t* __restrict__ ew) {
    __shared__ int any_nonzero;
    if (threadIdx.x == 0) any_nonzero = 0;
    __syncthreads();
    for (int i = threadIdx.x; i < 4096; i += blockDim.x) {
        if (ew[2 * i + 1] != 0u) any_nonzero = 1;
    }
    __syncthreads();
    if (threadIdx.x == 0) g_is64 = any_nonzero ? 0 : 1;
}

// ---------------------------------------------------------------------------
// K_tclear: reset the hash table (24 MB sequential) for this call/replay.
// ---------------------------------------------------------------------------
__global__ void k_tclear() {
    int i = blockIdx.x * blockDim.x + threadIdx.x;
    if (i < HCAP) {
        g_keys[i] = -1;
        g_sums[i] = 0.0f;
        g_cnts[i] = 0;
    }
}

// ---------------------------------------------------------------------------
// K_decode_noise: decode+clamp edge indices AND the partitionable threefry
// noise stream (bits = o0 ^ o1, counter (0, e)).
// ---------------------------------------------------------------------------
__global__ void k_decode_noise(const void* __restrict__ ei_raw) {
    int e = blockIdx.x * blockDim.x + threadIdx.x;
    if (e >= N_EDGES) return;
    int c, r;
    if (g_is64) {
        const long long* p = (const long long*)ei_raw;
        c = (int)p[e];
        r = (int)p[N_EDGES + e];
    } else {
        const int* p = (const int*)ei_raw;
        c = p[e];
        r = p[N_EDGES + e];
    }
    c = min(max(c, 0), N_NODES - 1);
    r = min(max(r, 0), N_NODES - 1);
    g_ci[e] = make_int2(c, r);

    uint32_t o0, o1;
    threefry2x32(0u, 42u, 0u, (uint32_t)e, o0, o1);
    g_noise[e] = noise_from_bits(o0 ^ o1);
}

// ---------------------------------------------------------------------------
// K_pre: A[n] = embed[n] @ W1[0:128], B[n] = embed[n] @ W1[128:256]
// ---------------------------------------------------------------------------
__global__ void __launch_bounds__(256) k_pre(const float* __restrict__ embed,
                                             const float* __restrict__ W1) {
    __shared__ float es[16 * D_EMB];                  // 8 KB
    int hq  = threadIdx.x & 15;
    int sub = threadIdx.x >> 4;
    int n0  = blockIdx.x * 16;

    const float4* emb4 = (const float4*)(embed + (size_t)n0 * D_EMB);
    float4* es4 = (float4*)es;
    es4[threadIdx.x]       = emb4[threadIdx.x];
    es4[threadIdx.x + 256] = emb4[threadIdx.x + 256];
    __syncthreads();

    const float4* W14 = (const float4*)W1;            // [256][16] float4
    float4 a = make_float4(0.f, 0.f, 0.f, 0.f);
    float4 b = make_float4(0.f, 0.f, 0.f, 0.f);
    const float* er = es + sub * D_EMB;
    #pragma unroll 4
    for (int d = 0; d < D_EMB; d++) {
        float  e  = er[d];
        float4 wa = __ldg(&W14[d * 16 + hq]);
        float4 wb = __ldg(&W14[(d + D_EMB) * 16 + hq]);
        a.x = fmaf(e, wa.x, a.x); a.y = fmaf(e, wa.y, a.y);
        a.z = fmaf(e, wa.z, a.z); a.w = fmaf(e, wa.w, a.w);
        b.x = fmaf(e, wb.x, b.x); b.y = fmaf(e, wb.y, b.y);
        b.z = fmaf(e, wb.z, b.z); b.w = fmaf(e, wb.w, b.w);
    }
    int n = n0 + sub;
    ((float4*)g_A)[n * 16 + hq] = a;
    ((float4*)g_B)[n * 16 + hq] = b;
}

// ---------------------------------------------------------------------------
// K_fused: (a) zero a 1250-float4 slab of d_out, (b) 8-lanes-per-edge MLP +
// concrete sample + hash-table insert (L2-resident, no DRAM atomics).
// ---------------------------------------------------------------------------
__global__ void __launch_bounds__(256) k_fused(const float* __restrict__ b1,
                                               const float* __restrict__ W2,
                                               const float* __restrict__ b2,
                                               float4* __restrict__ out) {
    // ---- zero slab (exact coverage, no bounds checks) ----
    const float4 z4 = make_float4(0.f, 0.f, 0.f, 0.f);
    size_t zbase = (size_t)blockIdx.x * ZPB4;
    #pragma unroll
    for (int i = 0; i < 4; i++)
        out[zbase + threadIdx.x + i * 256] = z4;
    if (threadIdx.x < ZPB4 - 1024)
        out[zbase + threadIdx.x + 1024] = z4;

    // ---- edge work: 4 edges per warp, 8 lanes per edge ----
    int warp = threadIdx.x >> 5;
    int lane = threadIdx.x & 31;
    int grp  = lane >> 3;          // edge within warp
    int l8   = lane & 7;           // h-octet: handles h in [l8*8, l8*8+8)
    int e    = blockIdx.x * EPB + warp * 4 + grp;

    int2 cr = g_ci[e];

    const float4* b14 = (const float4*)b1;
    const float4* w24 = (const float4*)W2;
    float4 b1a = __ldg(&b14[l8 * 2]);
    float4 b1b = __ldg(&b14[l8 * 2 + 1]);
    float4 w2a = __ldg(&w24[l8 * 2]);
    float4 w2b = __ldg(&w24[l8 * 2 + 1]);

    const float4* A4 = (const float4*)g_A;
    const float4* B4 = (const float4*)g_B;
    float4 av0 = A4[cr.x * 16 + l8 * 2];
    float4 av1 = A4[cr.x * 16 + l8 * 2 + 1];
    float4 bv0 = B4[cr.y * 16 + l8 * 2];
    float4 bv1 = B4[cr.y * 16 + l8 * 2 + 1];

    float s;
    s  = fmaxf(av0.x + bv0.x + b1a.x, 0.f) * w2a.x;
    s += fmaxf(av0.y + bv0.y + b1a.y, 0.f) * w2a.y;
    s += fmaxf(av0.z + bv0.z + b1a.z, 0.f) * w2a.z;
    s += fmaxf(av0.w + bv0.w + b1a.w, 0.f) * w2a.w;
    s += fmaxf(av1.x + bv1.x + b1b.x, 0.f) * w2b.x;
    s += fmaxf(av1.y + bv1.y + b1b.y, 0.f) * w2b.y;
    s += fmaxf(av1.z + bv1.z + b1b.z, 0.f) * w2b.z;
    s += fmaxf(av1.w + bv1.w + b1b.w, 0.f) * w2b.w;

    // reduce across the 8 lanes of this edge group
    s += __shfl_xor_sync(0xffffffffu, s, 1);
    s += __shfl_xor_sync(0xffffffffu, s, 2);
    s += __shfl_xor_sync(0xffffffffu, s, 4);

    if (l8 == 0) {
        float x = g_noise[e] + s + __ldg(&b2[0]);
        float v = 1.0f / (1.0f + expf(-x));     // sigmoid; -inf -> 0 exactly

        int key = cr.x * N_NODES + cr.y;
        uint32_t h = cell_hash(key);
        while (true) {
            int k = g_keys[h];
            if (k == key) break;
            if (k == -1) {
                int old = atomicCAS(&g_keys[h], -1, key);
                if (old == -1 || old == key) break;
            }
            h = (h + 1) & HMASK;
        }
        atomicAdd(&g_sums[h], v);
        atomicAdd(&g_cnts[h], 1);
        g_slot[e] = (int)h;
    }
}

// ---------------------------------------------------------------------------
// K_sym: per edge, idempotent plain store:
//   out[c,r] = cnt(c,r) * 0.5 * (S(c,r) + S(r,c))
// Duplicate edges at the same cell store the same value.
// ---------------------------------------------------------------------------
__global__ void k_sym(float* __restrict__ out) {
    int e = blockIdx.x * blockDim.x + threadIdx.x;
    if (e >= N_EDGES) return;
    int2 cr = g_ci[e];
    int slot = g_slot[e];
    float S   = g_sums[slot];
    int   cnt = g_cnts[slot];

    int tkey = cr.y * N_NODES + cr.x;
    float ST = 0.0f;
    uint32_t h = cell_hash(tkey);
    while (true) {
        int k = g_keys[h];
        if (k == tkey) { ST = g_sums[h]; break; }
        if (k == -1) break;
        h = (h + 1) & HMASK;
    }
    out[(size_t)cr.x * N_NODES + cr.y] = (float)cnt * 0.5f * (S + ST);
}

// ---------------------------------------------------------------------------
extern "C" void kernel_launch(void* const* d_in, const int* in_sizes, int n_in,
                              void* d_out, int out_size) {
    const float* embed = (const float*)d_in[0];
    const void*  ei    = d_in[1];
    const float* W1    = (const float*)d_in[2];
    const float* b1    = (const float*)d_in[3];
    const float* W2    = (const float*)d_in[4];
    const float* b2    = (const float*)d_in[5];
    float*       out   = (float*)d_out;

    // 0. dtype sniff + hash-table reset (24 MB sequential)
    k_detect<<<1, 256>>>((const uint32_t*)ei);
    k_tclear<<<(HCAP + 511) / 512, 512>>>();

    // 1. decode + clamp + threefry noise
    k_decode_noise<<<(N_EDGES + 255) / 256, 256>>>(ei);

    // 2. per-node halves of the first GEMM
    k_pre<<<N_NODES / 16, 256>>>(embed, W1);

    // 3. fused: zero d_out (400 MB) + edge MLP/sample + hash insert
    k_fused<<<FUSED_BLOCKS, 256>>>(b1, W2, b2, (float4*)out);

    // 4. symmetrize + multiplicity -> idempotent stores into output
    k_sym<<<(N_EDGES + 255) / 256, 256>>>(out);
}

// round 7
// speedup vs baseline: 1.6253x; 1.3752x over previous
#include <cuda_runtime.h>
#include <stdint.h>

// ---------------------------------------------------------------------------
// PGExplainer forward: masked_adj = adj * 0.5*(mask + mask^T)
// out[c,r] = cnt(c,r) * 0.5 * (S(c,r) + S(r,c)),  S = sum of sampled values
// Hash table keyed by cell id (c*N+r) holding (S, cnt); final write is an
// idempotent plain store (duplicate edges store the same value).
// ---------------------------------------------------------------------------

#define N_NODES 10000
#define N_EDGES 640000
#define D_EMB   128
#define HID     64

#define OUT_ELEMS ((size_t)N_NODES * N_NODES)   // 1e8 floats = 400 MB
#define OUT_F4    (OUT_ELEMS / 4)               // 25,000,000 float4

#define EPB          32                          // edges per block (8 warps x 4)
#define FUSED_BLOCKS (N_EDGES / EPB)             // 20,000
#define ZPB4         1250                        // float4 zero-slab per block (20000*1250 = 25M exact)

#define HCAP  (1 << 21)                          // hash capacity (2M slots)
#define HMASK (HCAP - 1)
#define HCAP4 (HCAP / 4)

#define DEC_BLOCKS ((N_EDGES + 255) / 256)       // 2500

// Scratch (device globals; hash table cleared at start of every call).
__device__ float g_A[N_NODES * HID];
__device__ float g_B[N_NODES * HID];
__device__ float g_noise[N_EDGES];
__device__ int2  g_ci[N_EDGES];        // decoded (col,row), clamped valid
__device__ int   g_slot[N_EDGES];      // hash slot of edge's own cell
__device__ int   g_is64;               // 1 if edge_index buffer is int64
__device__ int   g_keys[HCAP];         // -1 = empty
__device__ float g_sums[HCAP];
__device__ int   g_cnts[HCAP];

__device__ __forceinline__ uint32_t cell_hash(int key) {
    return ((uint32_t)key * 0x9E3779B1u) >> (32 - 21);   // top 21 bits
}

// ---------------------------------------------------------------------------
// threefry2x32 core (JAX rotation/key schedule), key = (0, 42)
// ---------------------------------------------------------------------------
__device__ __forceinline__ uint32_t rotl32(uint32_t x, int d) {
    return (x << d) | (x >> (32 - d));
}

__device__ __forceinline__ void threefry2x32(uint32_t k0, uint32_t k1,
                                             uint32_t x0, uint32_t x1,
                                             uint32_t& o0, uint32_t& o1) {
    uint32_t ks0 = k0, ks1 = k1, ks2 = k0 ^ k1 ^ 0x1BD11BDAu;
#define TF_R4(a, b, c, d)                            \
    x0 += x1; x1 = rotl32(x1, a); x1 ^= x0;          \
    x0 += x1; x1 = rotl32(x1, b); x1 ^= x0;          \
    x0 += x1; x1 = rotl32(x1, c); x1 ^= x0;          \
    x0 += x1; x1 = rotl32(x1, d); x1 ^= x0;
    x0 += ks0; x1 += ks1;
    TF_R4(13, 15, 26, 6);  x0 += ks1; x1 += ks2 + 1u;
    TF_R4(17, 29, 16, 24); x0 += ks2; x1 += ks0 + 2u;
    TF_R4(13, 15, 26, 6);  x0 += ks0; x1 += ks1 + 3u;
    TF_R4(17, 29, 16, 24); x0 += ks1; x1 += ks2 + 4u;
    TF_R4(13, 15, 26, 6);  x0 += ks2; x1 += ks0 + 5u;
#undef TF_R4
    o0 = x0; o1 = x1;
}

__device__ __forceinline__ float noise_from_bits(uint32_t bits) {
    float u = __uint_as_float((bits >> 9) | 0x3f800000u) - 1.0f;   // [0,1)
    return logf(u) - log1pf(-u);   // u==0 -> -inf -> sigmoid -> 0 (matches ref)
}

// ---------------------------------------------------------------------------
// K_detect: int64 vs int32 edge_index (int64 ids < 2^32 => odd words all 0).
// ---------------------------------------------------------------------------
__global__ void k_detect(const uint32_t* __restrict__ ew) {
    __shared__ int any_nonzero;
    if (threadIdx.x == 0) any_nonzero = 0;
    __syncthreads();
    for (int i = threadIdx.x; i < 4096; i += blockDim.x) {
        if (ew[2 * i + 1] != 0u) any_nonzero = 1;
    }
    __syncthreads();
    if (threadIdx.x == 0) g_is64 = any_nonzero ? 0 : 1;
}

// ---------------------------------------------------------------------------
// K_decode_noise: decode+clamp edge indices, partitionable threefry noise,
// AND clear the hash table (int4 slabs striped over the same grid).
// ---------------------------------------------------------------------------
__global__ void k_decode_noise(const void* __restrict__ ei_raw) {
    int e = blockIdx.x * blockDim.x + threadIdx.x;

    // --- table clear: first HCAP4 threads clear one int4 of each array ---
    if (e < HCAP4) {
        ((int4*)g_keys)[e]  = make_int4(-1, -1, -1, -1);
        ((float4*)g_sums)[e] = make_float4(0.f, 0.f, 0.f, 0.f);
        ((int4*)g_cnts)[e]  = make_int4(0, 0, 0, 0);
    }

    if (e >= N_EDGES) return;
    int c, r;
    if (g_is64) {
        const long long* p = (const long long*)ei_raw;
        c = (int)p[e];
        r = (int)p[N_EDGES + e];
    } else {
        const int* p = (const int*)ei_raw;
        c = p[e];
        r = p[N_EDGES + e];
    }
    c = min(max(c, 0), N_NODES - 1);
    r = min(max(r, 0), N_NODES - 1);
    g_ci[e] = make_int2(c, r);

    uint32_t o0, o1;
    threefry2x32(0u, 42u, 0u, (uint32_t)e, o0, o1);
    g_noise[e] = noise_from_bits(o0 ^ o1);
}

// ---------------------------------------------------------------------------
// K_pre: A[n] = embed[n] @ W1[0:128] (blockIdx.y=0), B likewise (y=1).
// Block = 32 nodes; thread = (hq, node-pair): each W1 float4 load feeds
// 8 FMAs (2 nodes x float4) -> FMA-issue dominated, near the ~10us fp32 floor.
// ---------------------------------------------------------------------------
__global__ void __launch_bounds__(256) k_pre(const float* __restrict__ embed,
                                             const float* __restrict__ W1) {
    __shared__ float es[32 * D_EMB];                  // 16 KB
    int hq  = threadIdx.x & 15;                       // h-quad: h = hq*4
    int gp  = threadIdx.x >> 4;                       // node-pair 0..15
    int n0  = blockIdx.x * 32;
    int half = blockIdx.y;                            // 0 = A, 1 = B

    // stage 32 embedding rows (4096 floats = 1024 float4), guard tail block
    const float4* emb4 = (const float4*)embed;
    size_t ebase = (size_t)n0 * (D_EMB / 4);
    float4* es4 = (float4*)es;
    #pragma unroll
    for (int i = 0; i < 4; i++) {
        size_t gidx = ebase + threadIdx.x + i * 256;
        if (gidx < (size_t)N_NODES * (D_EMB / 4))
            es4[threadIdx.x + i * 256] = emb4[gidx];
    }
    __syncthreads();

    const float4* W14 = (const float4*)(W1 + (size_t)half * D_EMB * HID);
    float4 a0 = make_float4(0.f, 0.f, 0.f, 0.f);
    float4 a1 = make_float4(0.f, 0.f, 0.f, 0.f);
    const float* er0 = es + (gp * 2)     * D_EMB;
    const float* er1 = es + (gp * 2 + 1) * D_EMB;
    #pragma unroll 8
    for (int d = 0; d < D_EMB; d++) {
        float4 w  = __ldg(&W14[d * 16 + hq]);
        float  e0 = er0[d];
        float  e1 = er1[d];
        a0.x = fmaf(e0, w.x, a0.x); a0.y = fmaf(e0, w.y, a0.y);
        a0.z = fmaf(e0, w.z, a0.z); a0.w = fmaf(e0, w.w, a0.w);
        a1.x = fmaf(e1, w.x, a1.x); a1.y = fmaf(e1, w.y, a1.y);
        a1.z = fmaf(e1, w.z, a1.z); a1.w = fmaf(e1, w.w, a1.w);
    }
    float4* dst = half ? (float4*)g_B : (float4*)g_A;
    int n = n0 + gp * 2;
    if (n < N_NODES)     dst[n * 16 + hq]       = a0;
    if (n + 1 < N_NODES) dst[(n + 1) * 16 + hq] = a1;
}

// ---------------------------------------------------------------------------
// K_fused: (a) zero a 1250-float4 slab of d_out with evict-first stores
// (keeps the hash table L2-resident), (b) 8-lanes-per-edge MLP + concrete
// sample + hash-table insert.
// ---------------------------------------------------------------------------
__global__ void __launch_bounds__(256) k_fused(const float* __restrict__ b1,
                                               const float* __restrict__ W2,
                                               const float* __restrict__ b2,
                                               float4* __restrict__ out) {
    // ---- zero slab (exact coverage, streaming stores) ----
    const float4 z4 = make_float4(0.f, 0.f, 0.f, 0.f);
    size_t zbase = (size_t)blockIdx.x * ZPB4;
    #pragma unroll
    for (int i = 0; i < 4; i++)
        __stcs(&out[zbase + threadIdx.x + i * 256], z4);
    if (threadIdx.x < ZPB4 - 1024)
        __stcs(&out[zbase + threadIdx.x + 1024], z4);

    // ---- edge work: 4 edges per warp, 8 lanes per edge ----
    int warp = threadIdx.x >> 5;
    int lane = threadIdx.x & 31;
    int grp  = lane >> 3;          // edge within warp
    int l8   = lane & 7;           // h-octet: handles h in [l8*8, l8*8+8)
    int e    = blockIdx.x * EPB + warp * 4 + grp;

    int2 cr = g_ci[e];

    const float4* b14 = (const float4*)b1;
    const float4* w24 = (const float4*)W2;
    float4 b1a = __ldg(&b14[l8 * 2]);
    float4 b1b = __ldg(&b14[l8 * 2 + 1]);
    float4 w2a = __ldg(&w24[l8 * 2]);
    float4 w2b = __ldg(&w24[l8 * 2 + 1]);

    const float4* A4 = (const float4*)g_A;
    const float4* B4 = (const float4*)g_B;
    float4 av0 = A4[cr.x * 16 + l8 * 2];
    float4 av1 = A4[cr.x * 16 + l8 * 2 + 1];
    float4 bv0 = B4[cr.y * 16 + l8 * 2];
    float4 bv1 = B4[cr.y * 16 + l8 * 2 + 1];

    float s;
    s  = fmaxf(av0.x + bv0.x + b1a.x, 0.f) * w2a.x;
    s += fmaxf(av0.y + bv0.y + b1a.y, 0.f) * w2a.y;
    s += fmaxf(av0.z + bv0.z + b1a.z, 0.f) * w2a.z;
    s += fmaxf(av0.w + bv0.w + b1a.w, 0.f) * w2a.w;
    s += fmaxf(av1.x + bv1.x + b1b.x, 0.f) * w2b.x;
    s += fmaxf(av1.y + bv1.y + b1b.y, 0.f) * w2b.y;
    s += fmaxf(av1.z + bv1.z + b1b.z, 0.f) * w2b.z;
    s += fmaxf(av1.w + bv1.w + b1b.w, 0.f) * w2b.w;

    // reduce across the 8 lanes of this edge group
    s += __shfl_xor_sync(0xffffffffu, s, 1);
    s += __shfl_xor_sync(0xffffffffu, s, 2);
    s += __shfl_xor_sync(0xffffffffu, s, 4);

    if (l8 == 0) {
        float x = g_noise[e] + s + __ldg(&b2[0]);
        float v = 1.0f / (1.0f + expf(-x));     // sigmoid; -inf -> 0 exactly

        int key = cr.x * N_NODES + cr.y;
        uint32_t h = cell_hash(key);
        while (true) {
            int k = g_keys[h];
            if (k == key) break;
            if (k == -1) {
                int old = atomicCAS(&g_keys[h], -1, key);
                if (old == -1 || old == key) break;
            }
            h = (h + 1) & HMASK;
        }
        atomicAdd(&g_sums[h], v);
        atomicAdd(&g_cnts[h], 1);
        g_slot[e] = (int)h;
    }
}

// ---------------------------------------------------------------------------
// K_sym: per edge, idempotent streaming store:
//   out[c,r] = cnt(c,r) * 0.5 * (S(c,r) + S(r,c))
// ---------------------------------------------------------------------------
__global__ void k_sym(float* __restrict__ out) {
    int e = blockIdx.x * blockDim.x + threadIdx.x;
    if (e >= N_EDGES) return;
    int2 cr = g_ci[e];
    int slot = g_slot[e];
    float S   = g_sums[slot];
    int   cnt = g_cnts[slot];

    int tkey = cr.y * N_NODES + cr.x;
    float ST = 0.0f;
    uint32_t h = cell_hash(tkey);
    while (true) {
        int k = g_keys[h];
        if (k == tkey) { ST = g_sums[h]; break; }
        if (k == -1) break;
        h = (h + 1) & HMASK;
    }
    __stcs(&out[(size_t)cr.x * N_NODES + cr.y], (float)cnt * 0.5f * (S + ST));
}

// ---------------------------------------------------------------------------
extern "C" void kernel_launch(void* const* d_in, const int* in_sizes, int n_in,
                              void* d_out, int out_size) {
    const float* embed = (const float*)d_in[0];
    const void*  ei    = d_in[1];
    const float* W1    = (const float*)d_in[2];
    const float* b1    = (const float*)d_in[3];
    const float* W2    = (const float*)d_in[4];
    const float* b2    = (const float*)d_in[5];
    float*       out   = (float*)d_out;

    // 0. dtype sniff
    k_detect<<<1, 256>>>((const uint32_t*)ei);

    // 1. decode + clamp + threefry noise + hash-table clear (one kernel)
    k_decode_noise<<<DEC_BLOCKS, 256>>>(ei);

    // 2. per-node halves of the first GEMM (A and B via blockIdx.y)
    {
        dim3 grid((N_NODES + 31) / 32, 2);
        k_pre<<<grid, 256>>>(embed, W1);
    }

    // 3. fused: zero d_out (400 MB, streaming) + edge MLP/sample + hash insert
    k_fused<<<FUSED_BLOCKS, 256>>>(b1, W2, b2, (float4*)out);

    // 4. symmetrize + multiplicity -> idempotent streaming stores
    k_sym<<<(N_EDGES + 255) / 256, 256>>>(out);
}